// round 13
// baseline (speedup 1.0000x reference)
#include <cuda_runtime.h>

// Problem constants (fixed by setup_inputs)
#define BB 4
#define LL 256
#define DMM 256
#define DLL 64
#define RRR 256
#define NROWS (BB*LL)        // 1024
#define KCAT 512

// ---------------------------------------------------------------------------
// Scratch (device globals — no allocation allowed)
// ---------------------------------------------------------------------------
__device__ float g_qz[NROWS * DMM];     // masked softmax(x)          (1 MB)
__device__ float g_sW[KCAT];            // (1/64) * sum_c W_t[c,d]
__device__ float g_u [BB * DMM];        // u[z,b] = sum_j qz[z,j,b]
__device__ float g_M [DMM * DMM];       // M[b][a] = sum_t sum_d V sW U

// ---------------------------------------------------------------------------
// Kernel 1: blocks [0,128)   = masked row softmax of x -> g_qz
//                               (warp per row, 8 rows/block, shuffle-only)
//           blocks [128,130) = sW[n=(t,d)] = (1/64)*sum_c W[t][c][d]
// ---------------------------------------------------------------------------
__global__ __launch_bounds__(256) void k_pre(const float* __restrict__ x,
                                             const int* __restrict__ mask,
                                             const float* __restrict__ W) {
    int tid = threadIdx.x;

    if (blockIdx.x >= 128) {
        int n = (blockIdx.x - 128) * 256 + tid;      // 0..511
        int t = n >> 8, d = n & 255;
        const float* w = W + t * DLL * RRR + d;
        float s = 0.0f;
        #pragma unroll 8
        for (int c = 0; c < DLL; c++) s += w[c * RRR];
        g_sW[n] = s * (1.0f / 64.0f);
        return;
    }

    int wid = tid >> 5, lane = tid & 31;
    int row = blockIdx.x * 8 + wid;

    const float4* xr = (const float4*)(x + row * DMM);
    float4 v0 = xr[lane];
    float4 v1 = xr[lane + 32];

    float m = fmaxf(fmaxf(fmaxf(v0.x, v0.y), fmaxf(v0.z, v0.w)),
                    fmaxf(fmaxf(v1.x, v1.y), fmaxf(v1.z, v1.w)));
    #pragma unroll
    for (int off = 16; off > 0; off >>= 1)
        m = fmaxf(m, __shfl_xor_sync(0xFFFFFFFFu, m, off));

    float4 e0 = make_float4(__expf(v0.x - m), __expf(v0.y - m),
                            __expf(v0.z - m), __expf(v0.w - m));
    float4 e1 = make_float4(__expf(v1.x - m), __expf(v1.y - m),
                            __expf(v1.z - m), __expf(v1.w - m));

    float s = e0.x + e0.y + e0.z + e0.w + e1.x + e1.y + e1.z + e1.w;
    #pragma unroll
    for (int off = 16; off > 0; off >>= 1)
        s += __shfl_xor_sync(0xFFFFFFFFu, s, off);

    float scale = (mask[row] != 0) ? (1.0f / s) : 0.0f;
    float4* qr = (float4*)(g_qz + row * DMM);
    qr[lane]      = make_float4(e0.x * scale, e0.y * scale, e0.z * scale, e0.w * scale);
    qr[lane + 32] = make_float4(e1.x * scale, e1.y * scale, e1.z * scale, e1.w * scale);
}

// ---------------------------------------------------------------------------
// Kernel 2: blocks [0,64):  M[b][a] = sum_t sum_d V[t][b][d]*sW[t*256+d]*U[t][a][d]
//                           (NT GEMM 256x256, K=512 concatenated over t;
//                            32x32 tiles, 2x2 acc, double-buffered)
//           blocks [64,96): u[z,b] = sum_j qz[z,j,b]
// ---------------------------------------------------------------------------
__global__ __launch_bounds__(256) void k_mid(const float* __restrict__ U,
                                             const float* __restrict__ V) {
    __shared__ __align__(16) float As[2][32][34];   // even pad: float2-safe
    __shared__ __align__(16) float Bs[2][32][34];
    __shared__ float sWs[KCAT];

    int tid = threadIdx.x;

    if (blockIdx.x >= 64) {                  // ---- u part ----
        int b = blockIdx.x - 64;             // 0..31
        int z = b >> 3;
        int c0 = (b & 7) * 32;
        int col = c0 + (tid & 31);
        int rg = tid >> 5;                   // 0..7
        const float* p = g_qz + (z * LL + rg * 32) * DMM + col;
        float s = 0.0f;
        #pragma unroll 8
        for (int j = 0; j < 32; j++) s += p[j * DMM];
        float* red = &As[0][0][0];           // reuse smem
        red[tid] = s;
        __syncthreads();
        if (tid < 32) {
            float t = 0.0f;
            #pragma unroll
            for (int g = 0; g < 8; g++) t += red[g * 32 + tid];
            g_u[z * DMM + c0 + tid] = t;
        }
        return;
    }

    // ---- M part ----
    const int b0 = (blockIdx.x >> 3) * 32;
    const int a0 = (blockIdx.x & 7) * 32;

    sWs[tid]       = g_sW[tid];
    sWs[256 + tid] = g_sW[256 + tid];
    __syncthreads();

    const int kk = tid & 31, rr = tid >> 5;      // loads: +8 per p
    const int tx = tid & 15, ty = tid >> 4;      // compute: 16x16, 2x2 acc

    float acc[2][2] = {};
    float ar[4], br[4];

    // prologue kb = 0 (t = 0)
    #pragma unroll
    for (int p = 0; p < 4; p++) {
        ar[p] = V[(b0 + rr + 8 * p) * RRR + kk];
        br[p] = U[(a0 + rr + 8 * p) * RRR + kk];
    }
    #pragma unroll
    for (int p = 0; p < 4; p++) {
        As[0][kk][rr + 8 * p] = ar[p] * sWs[kk];
        Bs[0][kk][rr + 8 * p] = br[p];
    }
    __syncthreads();

    int buf = 0;
    for (int kb = 0; kb < 16; kb++) {            // K = 512 over both t
        const int kn = (kb + 1) * 32;            // next k-block base
        if (kb < 15) {
            const float* Vn = V + (kn >> 8) * (DMM * RRR) + (kn & 255);
            const float* Un = U + (kn >> 8) * (DMM * RRR) + (kn & 255);
            #pragma unroll
            for (int p = 0; p < 4; p++) {
                ar[p] = Vn[(b0 + rr + 8 * p) * RRR + kk];
                br[p] = Un[(a0 + rr + 8 * p) * RRR + kk];
            }
        }
        #pragma unroll
        for (int k2 = 0; k2 < 32; k2++) {
            float2 a = *(const float2*)&As[buf][k2][ty * 2];
            float2 b = *(const float2*)&Bs[buf][k2][tx * 2];
            acc[0][0] = fmaf(a.x, b.x, acc[0][0]);
            acc[0][1] = fmaf(a.x, b.y, acc[0][1]);
            acc[1][0] = fmaf(a.y, b.x, acc[1][0]);
            acc[1][1] = fmaf(a.y, b.y, acc[1][1]);
        }
        if (kb < 15) {
            #pragma unroll
            for (int p = 0; p < 4; p++) {
                As[buf ^ 1][kk][rr + 8 * p] = ar[p] * sWs[kn + kk];
                Bs[buf ^ 1][kk][rr + 8 * p] = br[p];
            }
            __syncthreads();
            buf ^= 1;
        }
    }

    #pragma unroll
    for (int i = 0; i < 2; i++) {
        float2 v2 = make_float2(acc[i][0], acc[i][1]);
        *(float2*)&g_M[(b0 + ty * 2 + i) * DMM + a0 + tx * 2] = v2;
    }
}

// ---------------------------------------------------------------------------
// Kernel 3: out[row,a] = x[row,a] + valid_row * sum_k (u[z,k]-qz[row,k]) * M[k,a]
// Tiles 32(m) x 64(a), K=256 (BK=32, 8 k-blocks), 2x4 acc, double-buffered.
// Grid 128 = one wave.
// ---------------------------------------------------------------------------
__global__ __launch_bounds__(256) void k_out(const float* __restrict__ x,
                                             const int* __restrict__ mask,
                                             float* __restrict__ out) {
    __shared__ __align__(16) float As[2][32][34];   // [kk][mm], even pad
    __shared__ __align__(16) float Bs[2][32][64];   // [kk][aa]
    __shared__ float us[256];

    const int bx = blockIdx.x;
    const int m0 = (bx >> 2) * 32;
    const int a0 = (bx & 3) * 64;
    const int z  = m0 >> 8;
    const int tid = threadIdx.x;

    us[tid] = g_u[z * DMM + tid];
    __syncthreads();

    const int a_kk = tid & 31, a_mm = tid >> 5;     // A loads: +8 per p (4 ps)
    const int b_aa = tid & 63, b_kk = tid >> 6;     // B loads: +4 per p (8 ps)
    const int tx = tid & 15, ty = tid >> 4;         // compute: 2 rows x 4 cols

    float acc[2][4] = {};
    float ar[4], brM[8];

    // prologue kb = 0
    #pragma unroll
    for (int p = 0; p < 4; p++)
        ar[p] = g_qz[(m0 + a_mm + 8 * p) * DMM + a_kk];
    #pragma unroll
    for (int p = 0; p < 8; p++)
        brM[p] = g_M[(b_kk + 4 * p) * DMM + a0 + b_aa];
    #pragma unroll
    for (int p = 0; p < 4; p++)
        As[0][a_kk][a_mm + 8 * p] = us[a_kk] - ar[p];
    #pragma unroll
    for (int p = 0; p < 8; p++)
        Bs[0][b_kk + 4 * p][b_aa] = brM[p];
    __syncthreads();

    int buf = 0;
    for (int kb = 0; kb < 8; kb++) {
        const int k0n = (kb + 1) * 32;
        if (kb < 7) {
            #pragma unroll
            for (int p = 0; p < 4; p++)
                ar[p] = g_qz[(m0 + a_mm + 8 * p) * DMM + k0n + a_kk];
            #pragma unroll
            for (int p = 0; p < 8; p++)
                brM[p] = g_M[(k0n + b_kk + 4 * p) * DMM + a0 + b_aa];
        }
        #pragma unroll
        for (int k2 = 0; k2 < 32; k2++) {
            float2 a = *(const float2*)&As[buf][k2][ty * 2];
            float4 b = *(const float4*)&Bs[buf][k2][tx * 4];
            float av[2] = {a.x, a.y};
            float bv[4] = {b.x, b.y, b.z, b.w};
            #pragma unroll
            for (int i = 0; i < 2; i++)
                #pragma unroll
                for (int j = 0; j < 4; j++)
                    acc[i][j] = fmaf(av[i], bv[j], acc[i][j]);
        }
        if (kb < 7) {
            #pragma unroll
            for (int p = 0; p < 4; p++)
                As[buf ^ 1][a_kk][a_mm + 8 * p] = us[k0n + a_kk] - ar[p];
            #pragma unroll
            for (int p = 0; p < 8; p++)
                Bs[buf ^ 1][b_kk + 4 * p][b_aa] = brM[p];
            __syncthreads();
            buf ^= 1;
        }
    }

    #pragma unroll
    for (int i = 0; i < 2; i++) {
        int row = m0 + ty * 2 + i;
        float mv = (mask[row] != 0) ? 1.0f : 0.0f;
        float4 xv = *(const float4*)&x[row * DMM + a0 + tx * 4];
        float4 ov = make_float4(fmaf(mv, acc[i][0], xv.x),
                                fmaf(mv, acc[i][1], xv.y),
                                fmaf(mv, acc[i][2], xv.z),
                                fmaf(mv, acc[i][3], xv.w));
        *(float4*)&out[row * DMM + a0 + tx * 4] = ov;
    }
}

// ---------------------------------------------------------------------------
// Launch
// Inputs (metadata order): x (f32, 262144), U (f32, 131072), V (f32, 131072),
//                          W (f32, 32768),  mask (i32, 1024)
// ---------------------------------------------------------------------------
extern "C" void kernel_launch(void* const* d_in, const int* in_sizes, int n_in,
                              void* d_out, int out_size) {
    (void)in_sizes; (void)n_in; (void)out_size;
    const float* x    = (const float*)d_in[0];
    const float* U    = (const float*)d_in[1];
    const float* V    = (const float*)d_in[2];
    const float* W    = (const float*)d_in[3];
    const int*   mask = (const int*)d_in[4];
    float* out = (float*)d_out;

    k_pre<<<130, 256>>>(x, mask, W);
    k_mid<<<96, 256>>>(U, V);
    k_out<<<128, 256>>>(x, mask, out);
}